// round 10
// baseline (speedup 1.0000x reference)
#include <cuda_runtime.h>
#include <math.h>

// Problem constants (fixed by the dataset)
#define NN 8192          // atoms
#define NB 32            // graphs
#define NH 64            // hidden
#define NK 729           // 9^3 lattice points

#define TWO_PI  6.28318530717958647692f
#define FOUR_PI 12.5663706143591729539f

// half-space: lines 40..80 (m_i>0, or m_i==0 && m_j>0, plus (0,0,*) masked to m_z>0)
#define NLINES   41
#define NW_ITEMS (NB * NLINES * 9)          // 11808
#define WB ((NW_ITEMS + 63) / 64)           // 185 MLP blocks (launched first)
#define PB (NN / 64)                        // 128 phasor blocks

typedef unsigned long long u64;

// -------- device scratch (no allocations allowed) --------
__device__ float  g_vinv[NB];
__device__ int    g_off[NB + 1];
__device__ float  g_w[NB][NK];
__device__ float2 g_phas2[27][NN];   // unit phasors e^{i 2pi f_d m}, row-major over (d,m)

// ---------------- packed f32x2 helpers ----------------
__device__ __forceinline__ u64 pk2(float lo, float hi) {
    u64 r; asm("mov.b64 %0,{%1,%2};" : "=l"(r) : "f"(lo), "f"(hi)); return r;
}
__device__ __forceinline__ void upk2(u64 v, float& lo, float& hi) {
    asm("mov.b64 {%0,%1},%2;" : "=f"(lo), "=f"(hi) : "l"(v));
}
__device__ __forceinline__ u64 f2fma(u64 a, u64 b, u64 c) {
    u64 d; asm("fma.rn.f32x2 %0,%1,%2,%3;" : "=l"(d) : "l"(a), "l"(b), "l"(c)); return d;
}
__device__ __forceinline__ u64 f2add(u64 a, u64 b) {
    u64 d; asm("add.rn.f32x2 %0,%1,%2;" : "=l"(d) : "l"(a), "l"(b)); return d;
}
__device__ __forceinline__ u64 f2mul(u64 a, u64 b) {
    u64 d; asm("mul.rn.f32x2 %0,%1,%2;" : "=l"(d) : "l"(a), "l"(b)); return d;
}

// ---------------------------------------------------------------------------
// 3x3 inverse (double precision). Returns det.
// ---------------------------------------------------------------------------
__device__ __forceinline__ double inv3x3(const float* c, float* o)
{
    double a = c[0], b = c[1], cc = c[2];
    double d = c[3], e = c[4], f  = c[5];
    double g = c[6], h = c[7], i  = c[8];
    double A  = e * i - f * h;
    double Bv = f * g - d * i;
    double C  = d * h - e * g;
    double det = a * A + b * Bv + cc * C;
    double id = 1.0 / det;
    o[0] = (float)(A * id);
    o[1] = (float)((cc * h - b * i) * id);
    o[2] = (float)((b * f - cc * e) * id);
    o[3] = (float)(Bv * id);
    o[4] = (float)((a * i - cc * g) * id);
    o[5] = (float)((cc * d - a * f) * id);
    o[6] = (float)(C * id);
    o[7] = (float)((b * g - a * h) * id);
    o[8] = (float)((a * e - b * d) * id);
    return det;
}

// ---------------------------------------------------------------------------
// Fused prep kernel. Blocks [0,WB): MLP radial filter (half-space).
// Blocks [WB,WB+PB): per-atom phasors + batch offsets + out-zero.
// ---------------------------------------------------------------------------
__global__ void __launch_bounds__(64) k_prep(
    const float* __restrict__ pos, const int* __restrict__ batch,
    const float* __restrict__ cell,
    const float* __restrict__ W1, const float* __restrict__ B1,
    const float* __restrict__ W2, const float* __restrict__ B2,
    const float* __restrict__ W3, const float* __restrict__ B3,
    float* __restrict__ out)
{
    __shared__ float sInv[NB * 9];
    __shared__ __align__(16) float sW2T[NH * 72];   // row j padded to 72 floats
    __shared__ float sW1[3 * NH], sB1[NH], sB2[NH], sW3[NH];

    int tid = threadIdx.x;

    if (tid < NB) {
        double det = inv3x3(cell + tid * 9, &sInv[tid * 9]);
        if (blockIdx.x == 0) {
            double vol = fabs(det);
            if (vol < 1e-6) vol = 1e-6;
            g_vinv[tid] = (float)(1.0 / vol);
        }
    }

    if (blockIdx.x < WB) {
        // ---------------- MLP role ----------------
        for (int idx = tid; idx < 3 * NH; idx += 64) sW1[idx] = W1[idx];
        for (int idx = tid; idx < NH; idx += 64) {
            sB1[idx] = B1[idx]; sB2[idx] = B2[idx]; sW3[idx] = W3[idx];
        }
        for (int idx = tid; idx < NH * NH; idx += 64) {
            int i = idx >> 6, j = idx & 63;
            sW2T[j * 72 + i] = W2[idx];
        }
        __syncthreads();

        int g = blockIdx.x * 64 + tid;
        if (g >= NW_ITEMS) return;
        int b    = g / (NLINES * 9);
        int rem  = g - b * (NLINES * 9);
        int line = 40 + rem / 9;
        int z    = rem % 9;
        int ki = line / 9 - 4;
        int kj = line % 9 - 4;
        int kk = z - 4;
        const float* iv = &sInv[b * 9];
        float kc0 = TWO_PI * ((float)ki * iv[0] + (float)kj * iv[3] + (float)kk * iv[6]);
        float kc1 = TWO_PI * ((float)ki * iv[1] + (float)kj * iv[4] + (float)kk * iv[7]);
        float kc2 = TWO_PI * ((float)ki * iv[2] + (float)kj * iv[5] + (float)kk * iv[8]);
        float kn = sqrtf(kc0 * kc0 + kc1 * kc1 + kc2 * kc2);

        float w = 0.0f;
        bool active = (kn > 1e-6f) && !(line == 40 && z < 4);   // half-space mask
        if (active) {
            float x0 = log1pf(kn);
            float f0 = x0, f1 = x0 * x0, f2 = 1.0f / kn;
            u64 h1p[NH / 2];
            #pragma unroll
            for (int j = 0; j < NH; j += 2) {
                float a0 = fmaf(f0, sW1[j],     fmaf(f1, sW1[NH + j],     fmaf(f2, sW1[2 * NH + j],     sB1[j])));
                float a1 = fmaf(f0, sW1[j + 1], fmaf(f1, sW1[NH + j + 1], fmaf(f2, sW1[2 * NH + j + 1], sB1[j + 1])));
                float h0 = __fdividef(a0, 1.0f + __expf(-a0));   // silu
                float h1 = __fdividef(a1, 1.0f + __expf(-a1));
                h1p[j >> 1] = pk2(h0, h1);
            }
            float o = B3[0];
            for (int j = 0; j < NH; j++) {
                const ulonglong2* wr = (const ulonglong2*)&sW2T[j * 72];
                u64 acc0 = pk2(sB2[j], 0.0f);
                u64 acc1 = 0ULL;
                #pragma unroll
                for (int i2 = 0; i2 < 16; i2++) {
                    ulonglong2 wv = wr[i2];
                    acc0 = f2fma(h1p[2 * i2],     wv.x, acc0);
                    acc1 = f2fma(h1p[2 * i2 + 1], wv.y, acc1);
                }
                float p0, p1, q0, q1;
                upk2(acc0, p0, p1); upk2(acc1, q0, q1);
                float a = (p0 + p1) + (q0 + q1);
                float h2 = __fdividef(a, 1.0f + __expf(-a));     // silu
                o = fmaf(h2, sW3[j], o);
            }
            float sp = (o > 80.0f) ? o : log1pf(__expf(o));       // softplus
            w = (FOUR_PI / (kn * kn)) * sp;
        }
        g_w[b][line * 9 + z] = w;
    } else {
        // ---------------- phasor role ----------------
        __syncthreads();
        int n = (blockIdx.x - WB) * 64 + tid;
        out[n] = 0.0f;

        int b = batch[n];
        if (n == 0) {
            g_off[0] = 0;
            for (int bb = 1; bb <= b; bb++) g_off[bb] = 0;
        }
        if (n == NN - 1) {
            for (int bb = b + 1; bb <= NB; bb++) g_off[bb] = NN;
        } else {
            int b2 = batch[n + 1];
            for (int bb = b + 1; bb <= b2; bb++) g_off[bb] = n + 1;
        }

        float px = pos[3 * n], py = pos[3 * n + 1], pz = pos[3 * n + 2];
        const float* iv = &sInv[b * 9];
        #pragma unroll
        for (int d = 0; d < 3; d++) {
            float fr = px * iv[d] + py * iv[3 + d] + pz * iv[6 + d];
            float s, c;
            sincosf(TWO_PI * fr, &s, &c);
            float re[9], im[9];
            re[4] = 1.0f; im[4] = 0.0f;
            re[5] = c;    im[5] = s;
            #pragma unroll
            for (int m = 2; m <= 4; m++) {
                re[4 + m] = re[3 + m] * c - im[3 + m] * s;
                im[4 + m] = re[3 + m] * s + im[3 + m] * c;
            }
            #pragma unroll
            for (int m = 1; m <= 4; m++) { re[4 - m] = re[4 + m]; im[4 - m] = -im[4 + m]; }
            #pragma unroll
            for (int mi = 0; mi < 9; mi++) {
                float2 v; v.x = re[mi]; v.y = im[mi];
                g_phas2[d * 9 + mi][n] = v;
            }
        }
    }
}

// ---------------------------------------------------------------------------
// Fused main kernel: 64-thread block per (graph b, half-space line).
// Two warps split the atom range. Packed f32x2 accumulators (SC,SS) per
// (z, channel). Cross-lane reduction = distributed exchange (lane l ends
// owning value l) + 4-value butterfly tail + one smem round-trip that also
// combines the two warps. Factor 2 (half-space) cancels the 0.5.
// ---------------------------------------------------------------------------
__global__ void __launch_bounds__(64) k_main(const float* __restrict__ source,
                                             float* __restrict__ out)
{
    __shared__ u64 sS[2][36];

    int b    = blockIdx.x;
    int line = 40 + blockIdx.y;
    int w    = threadIdx.x >> 5;
    int lane = threadIdx.x & 31;
    int i4 = line / 9, j4 = line % 9;
    int start = g_off[b], end = g_off[b + 1];

    const float2* __restrict__ PX  = g_phas2[i4];
    const float2* __restrict__ PY  = g_phas2[9 + j4];
    const float2* __restrict__ PZ0 = g_phas2[18];      // m_z = -4
    const float2* __restrict__ PZS = g_phas2[23];      // m_z = +1
    const float4* __restrict__ SRC = (const float4*)source;

    u64 acc[36];            // packed (SC, SS) partials, index v = z*4 + c
    #pragma unroll
    for (int v = 0; v < 36; v++) acc[v] = 0ULL;

    // ---- pass 1: structure factors (this warp's atom share) ----
    {
        int a = start + lane + 32 * w;
        float2 LX, LY, LZ0, LZS; float4 LSV;
        if (a < end) { LX = PX[a]; LY = PY[a]; LZ0 = PZ0[a]; LZS = PZS[a]; LSV = SRC[a]; }
        while (a < end) {
            float2 X = LX, Y = LY, Z0 = LZ0, ZS = LZS; float4 sv = LSV;
            int an = a + 64;
            if (an < end) { LX = PX[an]; LY = PY[an]; LZ0 = PZ0[an]; LZS = PZS[an]; LSV = SRC[an]; }
            float c1r = X.x * Y.x - X.y * Y.y;
            float c1i = X.x * Y.y + X.y * Y.x;
            float cr = c1r * Z0.x - c1i * Z0.y;
            float ci = c1r * Z0.y + c1i * Z0.x;
            u64 p  = pk2(cr, ci);
            u64 s0 = pk2(sv.x, sv.x), s1 = pk2(sv.y, sv.y);
            u64 s2 = pk2(sv.z, sv.z), s3 = pk2(sv.w, sv.w);
            #pragma unroll
            for (int z = 0; z < 9; z++) {
                acc[z * 4 + 0] = f2fma(s0, p, acc[z * 4 + 0]);
                acc[z * 4 + 1] = f2fma(s1, p, acc[z * 4 + 1]);
                acc[z * 4 + 2] = f2fma(s2, p, acc[z * 4 + 2]);
                acc[z * 4 + 3] = f2fma(s3, p, acc[z * 4 + 3]);
                if (z < 8) {
                    float t = cr * ZS.x - ci * ZS.y;
                    ci = fmaf(cr, ZS.y, ci * ZS.x);
                    cr = t;
                    p = pk2(cr, ci);
                }
            }
            a = an;
        }
    }

    // ---- distributed exchange reduce on acc[0..31]: lane l ends with value l ----
    #pragma unroll
    for (int o = 16; o >= 1; o >>= 1) {
        bool hi = (lane & o) != 0;
        #pragma unroll
        for (int j = 0; j < o; j++) {
            u64 tlo = __shfl_xor_sync(0xffffffffu, acc[j],     o);
            u64 thi = __shfl_xor_sync(0xffffffffu, acc[j + o], o);
            acc[j] = hi ? f2add(acc[j + o], thi) : f2add(acc[j], tlo);
        }
    }
    sS[w][lane] = acc[0];
    // tail values 32..35 (z=8): full butterfly, all lanes end with totals
    #pragma unroll
    for (int o = 16; o; o >>= 1) {
        acc[32] = f2add(acc[32], __shfl_xor_sync(0xffffffffu, acc[32], o));
        acc[33] = f2add(acc[33], __shfl_xor_sync(0xffffffffu, acc[33], o));
        acc[34] = f2add(acc[34], __shfl_xor_sync(0xffffffffu, acc[34], o));
        acc[35] = f2add(acc[35], __shfl_xor_sync(0xffffffffu, acc[35], o));
    }
    if (lane < 4) {
        u64 qv = (lane == 0) ? acc[32] : (lane == 1) ? acc[33] : (lane == 2) ? acc[34] : acc[35];
        sS[w][32 + lane] = qv;
    }
    __syncthreads();

    // ---- combine the two warps + fold in w(k): Wp[v] = wz * (S0[v] + S1[v]) ----
    u64 Wp[36];
    #pragma unroll
    for (int z = 0; z < 9; z++) {
        float wzv = g_w[b][line * 9 + z];
        u64 wzp = pk2(wzv, wzv);
        #pragma unroll
        for (int c = 0; c < 4; c++) {
            int v = z * 4 + c;
            Wp[v] = f2mul(wzp, f2add(sS[0][v], sS[1][v]));
        }
    }
    float hv = g_vinv[b];   // 0.5 (energy) x 2 (half-space) = 1

    // ---- pass 2: per-atom energy from this line's 9 k's ----
    {
        int a = start + lane + 32 * w;
        float2 LX, LY, LZ0, LZS; float4 LSV;
        if (a < end) { LX = PX[a]; LY = PY[a]; LZ0 = PZ0[a]; LZS = PZS[a]; LSV = SRC[a]; }
        while (a < end) {
            float2 X = LX, Y = LY, Z0 = LZ0, ZS = LZS; float4 sv = LSV;
            int an = a + 64;
            if (an < end) { LX = PX[an]; LY = PY[an]; LZ0 = PZ0[an]; LZS = PZS[an]; LSV = SRC[an]; }
            float c1r = X.x * Y.x - X.y * Y.y;
            float c1i = X.x * Y.y + X.y * Y.x;
            float cr = c1r * Z0.x - c1i * Z0.y;
            float ci = c1r * Z0.y + c1i * Z0.x;
            u64 p = pk2(cr, ci);
            u64 E0 = 0ULL, E1 = 0ULL, E2 = 0ULL, E3 = 0ULL;
            #pragma unroll
            for (int z = 0; z < 9; z++) {
                E0 = f2fma(p, Wp[z * 4 + 0], E0);
                E1 = f2fma(p, Wp[z * 4 + 1], E1);
                E2 = f2fma(p, Wp[z * 4 + 2], E2);
                E3 = f2fma(p, Wp[z * 4 + 3], E3);
                if (z < 8) {
                    float t = cr * ZS.x - ci * ZS.y;
                    ci = fmaf(cr, ZS.y, ci * ZS.x);
                    cr = t;
                    p = pk2(cr, ci);
                }
            }
            float e0a, e0b, e1a, e1b, e2a, e2b, e3a, e3b;
            upk2(E0, e0a, e0b); upk2(E1, e1a, e1b);
            upk2(E2, e2a, e2b); upk2(E3, e3a, e3b);
            float e = sv.x * (e0a + e0b) + sv.y * (e1a + e1b)
                    + sv.z * (e2a + e2b) + sv.w * (e3a + e3b);
            atomicAdd(out + a, hv * e);
            a = an;
        }
    }
}

// ---------------------------------------------------------------------------
extern "C" void kernel_launch(void* const* d_in, const int* in_sizes, int n_in,
                              void* d_out, int out_size)
{
    const float* pos    = (const float*)d_in[0];
    const int*   batch  = (const int*)d_in[1];
    const float* cell   = (const float*)d_in[2];
    const float* source = (const float*)d_in[3];
    const float* W1 = (const float*)d_in[4];
    const float* B1 = (const float*)d_in[5];
    const float* W2 = (const float*)d_in[6];
    const float* B2 = (const float*)d_in[7];
    const float* W3 = (const float*)d_in[8];
    const float* B3 = (const float*)d_in[9];
    float* out = (float*)d_out;

    k_prep<<<WB + PB, 64>>>(pos, batch, cell, W1, B1, W2, B2, W3, B3, out);
    k_main<<<dim3(NB, NLINES), 64>>>(source, out);
}